// round 17
// baseline (speedup 1.0000x reference)
#include <cuda_runtime.h>
#include <cuda_bf16.h>
#include <cstdint>

// ---------------------------------------------------------------------------
// ResidualLogitAdapter — split pipeline v9 for GB300 (sm_103)
//   Kernel A (copyconf): out = z stream (skip in-domain), conf -> g_conf,
//                        folded weight prep (first 160 blocks).
//   Kernel B (gemm):     persistent CTAs (grid=296).  W1T resident in smem
//                        (staged once).  GEMM1 warp tile = 16 rows x 128
//                        cols (acc 64 regs); epilogue1 is register-only and
//                        produces GEMM2 A-fragments directly (no A2 smem).
//                        W2T cp.async'd per tile into the dead feats buffer.
// ---------------------------------------------------------------------------

namespace {

constexpr int ROWS_PER_CTA = 128;
constexpr int THREADS      = 256;
constexpr int N_ROWS       = 131072;
constexpr int N_WORK       = N_ROWS / ROWS_PER_CTA;   // 1024
constexpr int GEMM_CTAS    = 296;                     // 148 SMs x 2

// smem layout for gemm kernel (bytes)
constexpr unsigned OFF_CF    = 0;         // 128 float4                      2048
constexpr unsigned OFF_DOM   = 2048;      // 128 ints                         512
constexpr unsigned OFF_B1V   = 2560;      // 128 floats                       512
constexpr unsigned OFF_W256  = 3072;      // 128 floats                       512
constexpr unsigned OFF_W257  = 3584;      // 128 floats                       512
constexpr unsigned OFF_W258  = 4096;      // 128 floats                       512
constexpr unsigned OFF_B2V   = 4608;      // 64 floats                        256
constexpr unsigned OFF_SHA   = 5120;      // 2 chunks x [128 x 128B]        32768
                                          //   feats halves; then W2T (16KB)
constexpr unsigned OFF_SHB   = 38912;     // W1T resident: 4 x [128 x 128B] 65536
constexpr unsigned SMEM_TOTAL = 104448;   // ~102 KB -> 2 CTAs/SM

// Device-global scratch (no allocations allowed)
__device__ __nv_bfloat16 g_W1T[128 * 256];        // [h][f] = W1[f][h], f<256
__device__ __nv_bfloat16 g_W2T[64 * 128];         // [n][h] = W2[h][n]
__device__ __align__(16) float4 g_conf[N_ROWS];   // 2 MB: pmax,ent,marg,alpha

constexpr int PREP_ELEMS  = 128 * 256 + 64 * 128;   // 40960
constexpr int PREP_BLOCKS = PREP_ELEMS / 256;       // 160

__device__ __forceinline__ unsigned swz(unsigned o) { return o ^ ((o >> 3) & 0x70u); }

__device__ __forceinline__ void mma16816(float c[4], const unsigned a[4],
                                         unsigned b0, unsigned b1) {
    asm volatile(
        "mma.sync.aligned.m16n8k16.row.col.f32.bf16.bf16.f32 "
        "{%0,%1,%2,%3}, {%4,%5,%6,%7}, {%8,%9}, {%0,%1,%2,%3};"
        : "+f"(c[0]), "+f"(c[1]), "+f"(c[2]), "+f"(c[3])
        : "r"(a[0]), "r"(a[1]), "r"(a[2]), "r"(a[3]), "r"(b0), "r"(b1));
}

__device__ __forceinline__ void ldsm_x4(unsigned r[4], unsigned addr) {
    asm volatile(
        "ldmatrix.sync.aligned.m8n8.x4.shared.b16 {%0,%1,%2,%3}, [%4];"
        : "=r"(r[0]), "=r"(r[1]), "=r"(r[2]), "=r"(r[3]) : "r"(addr));
}

__device__ __forceinline__ void cp16(unsigned dst, const void* src) {
    asm volatile("cp.async.ca.shared.global [%0], [%1], 16;"
                 :: "r"(dst), "l"(src) : "memory");
}
__device__ __forceinline__ void cp_commit() {
    asm volatile("cp.async.commit_group;" ::: "memory");
}
template <int N>
__device__ __forceinline__ void cp_wait() {
    asm volatile("cp.async.wait_group %0;" :: "n"(N) : "memory");
}

// --------------------------- copy + conf kernel ----------------------------

__device__ __forceinline__ void handle_elem(const float4 v, size_t t,
                                            const int* __restrict__ dom,
                                            const float* __restrict__ alphas,
                                            float4* __restrict__ out4) {
    const int r  = (int)(t >> 7);
    const int c4 = (int)(t & 127u);
    const int d = dom[r];
    const int off4 = d * 16;
    const int rel = c4 - off4;
    if ((unsigned)rel >= 16u) {
        out4[t] = v;                      // out-of-domain: plain copy
        return;
    }
    const unsigned mask = 0xFFFFu << (off4 & 16);
    float hi1 = fmaxf(v.x, v.y), lo1 = fminf(v.x, v.y);
    float hi2 = fmaxf(v.z, v.w), lo2 = fminf(v.z, v.w);
    float m1 = fmaxf(hi1, hi2);
    float m2 = fmaxf(fminf(hi1, hi2), fmaxf(lo1, lo2));
#pragma unroll
    for (int s = 8; s > 0; s >>= 1) {
        float o1 = __shfl_xor_sync(mask, m1, s);
        float o2 = __shfl_xor_sync(mask, m2, s);
        float hi = fmaxf(m1, o1);
        float lo = fmaxf(fminf(m1, o1), fmaxf(m2, o2));
        m1 = hi; m2 = lo;
    }
    const float d0 = v.x - m1, d1 = v.y - m1, d2 = v.z - m1, d3 = v.w - m1;
    const float e0 = expf(d0), e1 = expf(d1), e2 = expf(d2), e3 = expf(d3);
    float S = (e0 + e1) + (e2 + e3);
    float T = (e0 * d0 + e1 * d1) + (e2 * d2 + e3 * d3);
#pragma unroll
    for (int s = 8; s > 0; s >>= 1) {
        S += __shfl_xor_sync(mask, S, s);
        T += __shfl_xor_sync(mask, T, s);
    }
    if (rel == 0) {
        const float inv = 1.0f / S;
        float4 cf;
        cf.x = inv;                          // p_max
        cf.y = logf(S) - T * inv;            // entropy
        cf.z = (1.0f - expf(m2 - m1)) * inv; // margin
        cf.w = alphas[d];
        g_conf[r] = cf;
    }
}

__global__ void __launch_bounds__(256)
copyconf_kernel(const float4* __restrict__ z4, const int* __restrict__ dom,
                const float* __restrict__ alphas,
                const float* __restrict__ W1, const float* __restrict__ W2,
                float4* __restrict__ out4) {
    const size_t t0 = (size_t)blockIdx.x * 512u + threadIdx.x;
    const size_t t1 = t0 + 256u;

    const float4 v0 = z4[t0];
    const float4 v1 = z4[t1];
    handle_elem(v0, t0, dom, alphas, out4);
    handle_elem(v1, t1, dom, alphas, out4);

    if (blockIdx.x < PREP_BLOCKS) {
        int i = blockIdx.x * 256 + threadIdx.x;
        if (i < 128 * 256) {
            int h = i >> 8, f = i & 255;
            g_W1T[i] = __float2bfloat16(W1[f * 128 + h]);
        } else {
            int i2 = i - 128 * 256;           // < 64*128
            int n = i2 >> 7, h = i2 & 127;
            g_W2T[i2] = __float2bfloat16(W2[h * 64 + n]);
        }
    }
}

// ------------------------------ gemm kernel --------------------------------
// Persistent: grid = 296 (2 CTAs/SM).  Warp w owns rows w*16..w*16+15.

__global__ void __launch_bounds__(THREADS, 2)
gemm_kernel(const float* __restrict__ z, const float* __restrict__ feats,
            const float* __restrict__ W1, const float* __restrict__ b1,
            const float* __restrict__ b2, const int* __restrict__ dom,
            float* __restrict__ out) {
    extern __shared__ char smem[];
    const int tid = threadIdx.x;
    const int wid = tid >> 5;
    const int lid = tid & 31;
    const int gid = lid >> 2;    // mma group id (0..7)
    const int tid4 = lid & 3;    // mma thread-in-group (0..3)
    const unsigned sbase = (unsigned)__cvta_generic_to_shared(smem);

    float4* cF    = (float4*)(smem + OFF_CF);
    int*   domS   = (int*)(smem + OFF_DOM);
    float* b1S    = (float*)(smem + OFF_B1V);
    float* w256S  = (float*)(smem + OFF_W256);
    float* w257S  = (float*)(smem + OFF_W257);
    float* w258S  = (float*)(smem + OFF_W258);
    float* b2S    = (float*)(smem + OFF_B2V);

    // ---- Once per CTA: stage resident W1T (64KB) via cp.async, and the
    //      loop-invariant bias/conf-weight vectors.
    const char* w1tB = (const char*)g_W1T;
    const char* w2tB = (const char*)g_W2T;
#pragma unroll
    for (int c = 0; c < 4; c++) {
#pragma unroll
        for (int u = 0; u < 4; u++) {
            const int j = tid + u * 256;          // 0..1023
            const unsigned hr  = (unsigned)(j >> 3);
            const unsigned off = (unsigned)(j & 7) * 16u;
            cp16(sbase + OFF_SHB + (unsigned)c * 16384u + swz(hr * 128u + off),
                 w1tB + hr * 512u + (unsigned)c * 128u + off);
        }
    }
    cp_commit();
    if (tid < 128) {
        b1S[tid]   = b1[tid];
        w256S[tid] = W1[256 * 128 + tid];
        w257S[tid] = W1[257 * 128 + tid];
        w258S[tid] = W1[258 * 128 + tid];
        if (tid < 64) b2S[tid] = b2[tid];
    }

    // ldmatrix lane-address components
    const int mrow = wid * 16;                     // warp's 16 rows
    const unsigned laneR  = (unsigned)(lid & 15);
    const unsigned laneHi = (unsigned)(lid >> 4);  // 0/1
    const unsigned offA = (unsigned)(mrow + laneR) * 128u + laneHi * 16u;
    const unsigned nLane  = laneHi * 8u + (unsigned)(lid & 7);
    const unsigned colHiB = ((unsigned)(lid >> 3) & 1u) * 16u;

    for (int work = blockIdx.x; work < N_WORK; work += GEMM_CTAS) {
        const int row0 = work * ROWS_PER_CTA;

        // ---- per-tile small staging (conf, dom)
        if (tid < 128) {
            cF[tid]   = g_conf[row0 + tid];
            domS[tid] = dom[row0 + tid] * 64;
        }

        float acc[16][4];
#pragma unroll
        for (int ni = 0; ni < 16; ni++)
#pragma unroll
            for (int q = 0; q < 4; q++) acc[ni][q] = 0.0f;

        // ---- GEMM1 over two feats halves (K 0..127, 128..255) through SHA.
#pragma unroll 1
        for (int half = 0; half < 2; half++) {
            // stage feats half: k4 in [half*32, half*32+32)
            const float4* fv = (const float4*)feats + (size_t)row0 * 64 + half * 32;
#pragma unroll 1
            for (int batch = 0; batch < 2; batch++) {
                float4 vb[8];
#pragma unroll
                for (int u = 0; u < 8; u++) {
                    const int j = (batch * 8 + u) * 256 + tid;   // 0..8191
                    const int r = j >> 5, k4h = j & 31;
                    vb[u] = fv[(size_t)r * 64 + k4h];
                }
#pragma unroll
                for (int u = 0; u < 8; u++) {
                    const int j = (batch * 8 + u) * 256 + tid;
                    const int r = j >> 5, k4h = j & 31;
                    const unsigned chunk = (unsigned)(k4h >> 4);
                    const unsigned kb = (unsigned)((k4h & 15) << 3);
                    __nv_bfloat162 p0 = __floats2bfloat162_rn(vb[u].x, vb[u].y);
                    __nv_bfloat162 p1 = __floats2bfloat162_rn(vb[u].z, vb[u].w);
                    uint2 w;
                    w.x = *(unsigned*)&p0; w.y = *(unsigned*)&p1;
                    *(uint2*)(smem + OFF_SHA + chunk * 16384u +
                              swz((unsigned)r * 128u + kb)) = w;
                }
            }
            if (half == 0) cp_wait<0>();   // W1T resident (first tile only real)
            __syncthreads();               // feats half + cF/domS published

            // two K-chunks of this half; B from resident W1T (no barriers)
#pragma unroll
            for (int kc = 0; kc < 2; kc++) {
                const int kcg = half * 2 + kc;
                const unsigned aB = sbase + OFF_SHA + (unsigned)kc * 16384u;
                const unsigned bB = sbase + OFF_SHB + (unsigned)kcg * 16384u;
#pragma unroll
                for (int ks = 0; ks < 4; ks++) {
                    const unsigned kt = (unsigned)ks * 32u;
                    unsigned a0[4];
                    ldsm_x4(a0, aB + swz(offA + kt));
#pragma unroll
                    for (int j = 0; j < 8; j++) {
                        unsigned bb[4];
                        const unsigned offB =
                            (unsigned)(j * 16) * 128u + nLane * 128u + colHiB;
                        ldsm_x4(bb, bB + swz(offB + kt));
                        mma16816(acc[2 * j],     a0, bb[0], bb[1]);
                        mma16816(acc[2 * j + 1], a0, bb[2], bb[3]);
                    }
                }
            }
            __syncthreads();   // done reading SHA before restage / W2T
        }

        // ---- Issue W2T cp.async into SHA (feats dead); hide under epilogue1.
#pragma unroll
        for (int u = 0; u < 4; u++) {
            const int j = tid + u * 256;          // 0..1023
            const unsigned nr  = (unsigned)(j >> 4);          // 0..63
            const unsigned c   = ((unsigned)j >> 3) & 1u;     // k-chunk
            const unsigned off = (unsigned)(j & 7) * 16u;
            cp16(sbase + OFF_SHA + c * 8192u + swz(nr * 128u + off),
                 w2tB + nr * 256u + c * 128u + off);
        }
        cp_commit();

        // ---- Epilogue1 (registers only): h = relu(acc + b1 + c@W1[256:259]);
        //      pack directly into GEMM2 A-fragments.
        unsigned a2f[32];
        {
            const int rA = mrow + gid;
            const float4 cfa = cF[rA];
            const float4 cfb = cF[rA + 8];
#pragma unroll
            for (int t = 0; t < 8; t++) {
#pragma unroll
                for (int hbit = 0; hbit < 2; hbit++) {
                    const int ni = 2 * t + hbit;
                    const int j = ni * 8 + tid4 * 2;       // global h col (even)
                    const float bj0 = b1S[j],     bj1 = b1S[j + 1];
                    const float wa0 = w256S[j],   wa1 = w256S[j + 1];
                    const float wb0 = w257S[j],   wb1 = w257S[j + 1];
                    const float wc0 = w258S[j],   wc1 = w258S[j + 1];
                    float v0 = acc[ni][0] + bj0 + cfa.x * wa0 + cfa.y * wb0 + cfa.z * wc0;
                    float v1 = acc[ni][1] + bj1 + cfa.x * wa1 + cfa.y * wb1 + cfa.z * wc1;
                    float v2 = acc[ni][2] + bj0 + cfb.x * wa0 + cfb.y * wb0 + cfb.z * wc0;
                    float v3 = acc[ni][3] + bj1 + cfb.x * wa1 + cfb.y * wb1 + cfb.z * wc1;
                    v0 = fmaxf(v0, 0.0f); v1 = fmaxf(v1, 0.0f);
                    v2 = fmaxf(v2, 0.0f); v3 = fmaxf(v3, 0.0f);
                    __nv_bfloat162 pA = __floats2bfloat162_rn(v0, v1);  // row gid
                    __nv_bfloat162 pB = __floats2bfloat162_rn(v2, v3);  // row gid+8
                    a2f[t * 4 + hbit * 2 + 0] = *(unsigned*)&pA;
                    a2f[t * 4 + hbit * 2 + 1] = *(unsigned*)&pB;
                }
            }
        }
        cp_wait<0>();        // W2T arrived
        __syncthreads();

        // ---- GEMM2  dz[16,64] per warp = h_regs @ W2;  B (W2T) in SHA.
        {
            float acc2[8][4];
#pragma unroll
            for (int ni = 0; ni < 8; ni++)
#pragma unroll
                for (int q = 0; q < 4; q++) acc2[ni][q] = 0.0f;

            // Prefetch epilogue2 z-rereads (latency hides under MMAs).
            const int rA = mrow + gid;
            float2 pzA[8], pzB[8];
            {
                const float* zA = z + (size_t)(row0 + rA) * 512 + domS[rA];
                const float* zB = z + (size_t)(row0 + rA + 8) * 512 + domS[rA + 8];
#pragma unroll
                for (int nj = 0; nj < 8; nj++) {
                    const int j = nj * 8 + tid4 * 2;
                    pzA[nj] = *(const float2*)(zA + j);
                    pzB[nj] = *(const float2*)(zB + j);
                }
            }

#pragma unroll
            for (int t = 0; t < 8; t++) {                 // k16 block
                const unsigned bB = sbase + OFF_SHA + (unsigned)(t >> 2) * 8192u;
                const unsigned kt = (unsigned)(t & 3) * 32u;
#pragma unroll
                for (int j = 0; j < 4; j++) {             // n-group pairs
                    unsigned bb[4];
                    const unsigned offB =
                        (unsigned)(j * 16) * 128u + nLane * 128u + colHiB;
                    ldsm_x4(bb, bB + swz(offB + kt));
                    mma16816(acc2[2 * j],     a2f + t * 4, bb[0], bb[1]);
                    mma16816(acc2[2 * j + 1], a2f + t * 4, bb[2], bb[3]);
                }
            }

            // ---- Epilogue2: out[in-domain] = z + (dz + b2) * alpha.
            const float alA = cF[rA].w;
            const float alB = cF[rA + 8].w;
            float* outA = out + (size_t)(row0 + rA) * 512 + domS[rA];
            float* outB = out + (size_t)(row0 + rA + 8) * 512 + domS[rA + 8];
#pragma unroll
            for (int nj = 0; nj < 8; nj++) {
                const int j = nj * 8 + tid4 * 2;
                const float bj0 = b2S[j], bj1 = b2S[j + 1];
                float2 oA, oB;
                oA.x = pzA[nj].x + (acc2[nj][0] + bj0) * alA;
                oA.y = pzA[nj].y + (acc2[nj][1] + bj1) * alA;
                oB.x = pzB[nj].x + (acc2[nj][2] + bj0) * alB;
                oB.y = pzB[nj].y + (acc2[nj][3] + bj1) * alB;
                *(float2*)(outA + j) = oA;
                *(float2*)(outB + j) = oB;
            }
        }

        // Protect SHA (W2T) / cF / domS before next tile's writes.
        __syncthreads();
    }
}

}  // namespace

// ------------------------------ launch -------------------------------------

extern "C" void kernel_launch(void* const* d_in, const int* in_sizes, int n_in,
                              void* d_out, int out_size) {
    const float* z      = (const float*)d_in[0];
    const float* feats  = (const float*)d_in[1];
    const float* W1     = (const float*)d_in[2];
    const float* b1     = (const float*)d_in[3];
    const float* W2     = (const float*)d_in[4];
    const float* b2     = (const float*)d_in[5];
    const float* alphas = (const float*)d_in[6];
    const int*   dom    = (const int*)d_in[7];
    float* out = (float*)d_out;

    cudaFuncSetAttribute(gemm_kernel, cudaFuncAttributeMaxDynamicSharedMemorySize,
                         SMEM_TOTAL);

    copyconf_kernel<<<N_ROWS * 128 / 512, 256>>>((const float4*)z, dom, alphas,
                                                 W1, W2, (float4*)out);
    gemm_kernel<<<GEMM_CTAS, THREADS, SMEM_TOTAL>>>(z, feats, W1, b1, b2, dom, out);
}